// round 11
// baseline (speedup 1.0000x reference)
#include <cuda_runtime.h>
#include <math.h>

static constexpr int NN = 100000;   // nodes (capacity)
static constexpr int EE = 1600000;  // edges (capacity)
static constexpr int DD = 64;
static constexpr int SCAN_B = 1024;
static constexpr int NB_MAX = (NN + SCAN_B - 1) / SCAN_B;   // <= 98 for N=100K

// Scratch (static device globals; no allocation anywhere).
// State invariants are self-restoring per launch: cnt re-zeroed by k_scanfused,
// sf/st re-zeroed by k_seg, barrier reset by k_histnode -> graph replays OK.
__device__ __align__(16) float  g_z[(size_t)NN * DD];  // 25.6 MB z result
__device__ float  g_as[NN], g_ad[NN];                  // per-node logit halves
__device__ float  g_norm[NN];                          // ||tax_n||
__device__ int    g_Mi;                                // max norm (float bits; pos -> int cmp ok)
__device__ int    g_cnt[NN];                           // in-degree histogram (zero at launch start)
__device__ int    g_off[NN];                           // CSR row start
__device__ int    g_pos[NN];                           // scatter cursor -> row end
__device__ float  g_sf[NN], g_st[NN];                  // softmax denominators (zero at launch start)
__device__ __align__(8) float2 g_e2[EE];               // (e_f, e_t) in CSR order
__device__ int    g_src2[EE];                          // src in CSR order
__device__ int    g_bsum[NB_MAX];                      // block sums for scan
__device__ int    g_barrier;                           // grid barrier counter

// ---------------------------------------------------------------------------
// K1: fused dst-histogram + per-node dots a_s, a_d + ||tax|| + global max norm
__global__ void k_histnode(const float* __restrict__ h, const float* __restrict__ tax,
                           const float* __restrict__ wh, const int* __restrict__ dst,
                           int n, int e) {
    int gt = blockIdx.x * blockDim.x + threadIdx.x;
    if (gt == 0) g_barrier = 0;
    if (gt < e) atomicAdd(&g_cnt[dst[gt]], 1);        // cnt==0 invariant at start
    int w = gt >> 5, lane = gt & 31;
    if (w >= n) return;
    float2 hv = *reinterpret_cast<const float2*>(h + (size_t)w * DD + lane * 2);
    float2 tv = *reinterpret_cast<const float2*>(tax + (size_t)w * DD + lane * 2);
    float2 wa = *reinterpret_cast<const float2*>(wh + lane * 2);
    float2 wb = *reinterpret_cast<const float2*>(wh + DD + lane * 2);
    float ps = hv.x * wa.x + hv.y * wa.y;
    float pd = hv.x * wb.x + hv.y * wb.y;
    float nq = tv.x * tv.x + tv.y * tv.y;
#pragma unroll
    for (int o = 16; o; o >>= 1) {
        ps += __shfl_xor_sync(0xffffffffu, ps, o);
        pd += __shfl_xor_sync(0xffffffffu, pd, o);
        nq += __shfl_xor_sync(0xffffffffu, nq, o);
    }
    if (lane == 0) {
        g_as[w] = ps;
        g_ad[w] = pd;
        float nr = sqrtf(nq);
        g_norm[w] = nr;
        atomicMax(&g_Mi, __float_as_int(nr));          // idempotent across replays
    }
}

// K2: fused exclusive scan (98 co-resident blocks, manual grid barrier);
//     re-zeroes g_cnt after consuming it (restores invariant for next launch)
__global__ void k_scanfused(int n, int nb) {
    __shared__ int sh[SCAN_B];
    __shared__ int bsc[128];
    __shared__ int base;
    int bid = blockIdx.x;
    int i = bid * SCAN_B + threadIdx.x;
    int v = (i < n) ? g_cnt[i] : 0;
    sh[threadIdx.x] = v;
    __syncthreads();
#pragma unroll
    for (int d = 1; d < SCAN_B; d <<= 1) {
        int u = (threadIdx.x >= d) ? sh[threadIdx.x - d] : 0;
        __syncthreads();
        sh[threadIdx.x] += u;
        __syncthreads();
    }
    if (threadIdx.x == SCAN_B - 1) {
        g_bsum[bid] = sh[SCAN_B - 1];
        __threadfence();
        atomicAdd(&g_barrier, 1);
    }
    if (threadIdx.x == 0) {
        while (atomicAdd(&g_barrier, 0) < nb) __nanosleep(64);
    }
    __syncthreads();
    if (threadIdx.x < nb) bsc[threadIdx.x] = g_bsum[threadIdx.x];
    __syncthreads();
    if (threadIdx.x == 0) {
        int s = 0;
        for (int k = 0; k < bid; k++) s += bsc[k];
        base = s;
    }
    __syncthreads();
    if (i < n) {
        int off = base + sh[threadIdx.x] - v;   // exclusive
        g_off[i] = off;
        g_pos[i] = off;
        g_cnt[i] = 0;                            // restore invariant
    }
}

// K3: fused edge pass, all fp32. Per-dst shift S_d = ||tax_d||*M - 80
// (d-only -> cancels in softmax; Cauchy-Schwarz bounds p-S_d in [-~64, 80])
__global__ void k_edge(const float* __restrict__ tax, const int* __restrict__ src,
                       const int* __restrict__ dst, int e) {
    int gt = blockIdx.x * blockDim.x + threadIdx.x;
    int w = gt >> 3, l = gt & 7;
    if (w >= e) return;
    int s = src[w], d = dst[w];
    const float4* ts = reinterpret_cast<const float4*>(tax + (size_t)s * DD);
    const float4* td = reinterpret_cast<const float4*>(tax + (size_t)d * DD);
    float4 a0 = ts[l * 2],     b0 = td[l * 2];
    float4 a1 = ts[l * 2 + 1], b1 = td[l * 2 + 1];
    float p = a0.x * b0.x + a0.y * b0.y + a0.z * b0.z + a0.w * b0.w
            + a1.x * b1.x + a1.y * b1.y + a1.z * b1.z + a1.w * b1.w;
#pragma unroll
    for (int o = 4; o; o >>= 1) p += __shfl_xor_sync(0xffffffffu, p, o);
    if (l == 0) {
        float x = g_as[s] + g_ad[d];
        float wf = x >= 0.f ? x : 0.01f * x;      // leaky_relu(0.01); |wf| small
        float M = __int_as_float(g_Mi);
        float shift = g_norm[d] * M - 80.f;
        float ef = __expf(wf);
        float et = __expf(p - shift);
        atomicAdd(&g_sf[d], ef);
        atomicAdd(&g_st[d], et);
        int pos = atomicAdd(&g_pos[d], 1);
        g_e2[pos] = make_float2(ef, et);
        g_src2[pos] = s;
    }
}

// K4 (PROFILED SLOT): segment aggregation, broadcast scheme.
// Lanes coalesce-load 32 (src, alpha) entries, then shfl-broadcast to drive
// independent full-row h gathers (unroll 4 -> 4 rows in flight, no ptr-chase).
// Re-zeroes sf/st after reading (restores invariant).
__global__ void k_seg(const float* __restrict__ h, int n) {
    int gt = blockIdx.x * blockDim.x + threadIdx.x;
    int w = gt >> 5, lane = gt & 31;
    if (w >= n) return;
    int r0 = g_off[w], r1 = g_pos[w];   // cursor == segment end after scatter
    float sfv = g_sf[w], stv = g_st[w];
    if (lane == 0) { g_sf[w] = 0.f; g_st[w] = 0.f; }   // restore invariant
    float2 acc = make_float2(0.f, 0.f);
    if (r1 > r0) {
        float isf = 0.5f / sfv, ist = 0.5f / stv;
        for (int base = r0; base < r1; base += 32) {
            int m = r1 - base; if (m > 32) m = 32;
            int sj = 0; float aj = 0.f;
            if (lane < m) {
                sj = g_src2[base + lane];
                float2 ej = g_e2[base + lane];
                aj = ej.x * isf + ej.y * ist;
            }
            int k = 0;
            for (; k + 4 <= m; k += 4) {
                int   s0 = __shfl_sync(0xffffffffu, sj, k);
                int   s1 = __shfl_sync(0xffffffffu, sj, k + 1);
                int   s2 = __shfl_sync(0xffffffffu, sj, k + 2);
                int   s3 = __shfl_sync(0xffffffffu, sj, k + 3);
                float a0 = __shfl_sync(0xffffffffu, aj, k);
                float a1 = __shfl_sync(0xffffffffu, aj, k + 1);
                float a2 = __shfl_sync(0xffffffffu, aj, k + 2);
                float a3 = __shfl_sync(0xffffffffu, aj, k + 3);
                float2 h0 = *reinterpret_cast<const float2*>(h + (size_t)s0 * DD + lane * 2);
                float2 h1 = *reinterpret_cast<const float2*>(h + (size_t)s1 * DD + lane * 2);
                float2 h2 = *reinterpret_cast<const float2*>(h + (size_t)s2 * DD + lane * 2);
                float2 h3 = *reinterpret_cast<const float2*>(h + (size_t)s3 * DD + lane * 2);
                acc.x += a0 * h0.x + a1 * h1.x + a2 * h2.x + a3 * h3.x;
                acc.y += a0 * h0.y + a1 * h1.y + a2 * h2.y + a3 * h3.y;
            }
            for (; k < m; k++) {
                int   s = __shfl_sync(0xffffffffu, sj, k);
                float a = __shfl_sync(0xffffffffu, aj, k);
                float2 hv = *reinterpret_cast<const float2*>(h + (size_t)s * DD + lane * 2);
                acc.x += a * hv.x;
                acc.y += a * hv.y;
            }
        }
    }
    *reinterpret_cast<float2*>(g_z + (size_t)w * DD + lane * 2) = acc;
}

// K5: out = z @ W^T + b   (block = (64,4); W transposed in smem, conflict-free)
__global__ void k_out(const float* __restrict__ Ww, const float* __restrict__ Wb,
                      float* __restrict__ out, int n) {
    __shared__ float Ws[DD * DD];   // Ws[k*64 + c] = Ww[c*64 + k]
    __shared__ float bs[DD];
    int tid = threadIdx.y * 64 + threadIdx.x;
    for (int i = tid; i < DD * DD; i += 256) {
        int c = i >> 6, k = i & 63;
        Ws[k * DD + c] = Ww[i];
    }
    if (tid < DD) bs[tid] = Wb[tid];
    __syncthreads();
    int row = blockIdx.x * 4 + threadIdx.y;
    if (row >= n) return;
    int c = threadIdx.x;
    const float* zr = g_z + (size_t)row * DD;
    float acc = bs[c];
#pragma unroll
    for (int k = 0; k < DD; k += 4) {
        float4 zv = *reinterpret_cast<const float4*>(zr + k);
        acc += zv.x * Ws[(k + 0) * DD + c];
        acc += zv.y * Ws[(k + 1) * DD + c];
        acc += zv.z * Ws[(k + 2) * DD + c];
        acc += zv.w * Ws[(k + 3) * DD + c];
    }
    out[(size_t)row * DD + c] = acc;
}

// ---------------------------------------------------------------------------
extern "C" void kernel_launch(void* const* d_in, const int* in_sizes, int n_in,
                              void* d_out, int out_size) {
    const float* h   = (const float*)d_in[0];
    const float* tax = (const float*)d_in[1];
    const int*   src = (const int*)d_in[2];
    const int*   dst = (const int*)d_in[3];
    const float* wh  = (const float*)d_in[4];
    const float* Ww  = (const float*)d_in[5];
    const float* Wb  = (const float*)d_in[6];
    float* out = (float*)d_out;

    int n = in_sizes[0] / DD;
    int e = in_sizes[2];
    int nb = (n + SCAN_B - 1) / SCAN_B;   // 98 for N=100K (all co-resident)

    k_histnode<<<(int)(((long long)n * 32 + 255) / 256), 256>>>(h, tax, wh, dst, n, e); // 1
    k_scanfused<<<nb, SCAN_B>>>(n, nb);                                                 // 2
    k_edge<<<(int)(((long long)e * 8 + 255) / 256), 256>>>(tax, src, dst, e);           // 3
    k_seg<<<(int)(((long long)n * 32 + 255) / 256), 256>>>(h, n);                       // 4 <- profiled
    k_out<<<(n + 3) / 4, dim3(64, 4)>>>(Ww, Wb, out, n);                                // 5
}